// round 9
// baseline (speedup 1.0000x reference)
#include <cuda_runtime.h>
#include <cstdint>
#include <cstdio>

#define N_ANCH   300000
#define N_CLS    80
#define DET_DIM  85
#define TOPK     1000
#define MAXBOX   300
#define CAP      4096
#define NMS_THR  0.4f

#define GRIDB    148
#define NTHR     1024
#define NWARPS   (GRIDB * (NTHR / 32))     // 4736
#define NCH16    (N_ANCH / 16)             // 18750 (exact)
#define DYN_BYTES (TOPK * 32 * 4)          // 128000 B (P5 sort 32K, P7 mask 125K)

// ---------------- device scratch ----------------
__device__ unsigned int       g_scores[N_ANCH];
__device__ unsigned int       g_histA[256];
__device__ unsigned int       g_histB[256];
__device__ unsigned int       g_histC[256];
__device__ int                g_cand_cnt;
__device__ unsigned long long g_cand[CAP];
__device__ int                g_topk_idx[TOPK];
__device__ float4             g_boxk[TOPK];
__device__ unsigned int       g_maskmat[32 * TOPK];   // TRANSPOSED: [colword][row]
__device__ unsigned int       g_bar_count;
__device__ unsigned int       g_bar_gen;

// ---------------- grid barrier ----------------
__device__ __forceinline__ void gbar(unsigned int base, unsigned int k, bool wait) {
    __syncthreads();
    if (threadIdx.x == 0) {
        __threadfence();
        unsigned int a = atomicAdd(&g_bar_count, 1u) + 1u;
        if (a == GRIDB) {
            g_bar_count = 0u;
            __threadfence();
            atomicExch(&g_bar_gen, base + k);
        } else if (wait) {
            const volatile unsigned int* vg = &g_bar_gen;
            while (*vg - base < k) __nanosleep(64);
            __threadfence();
        }
    }
    __syncthreads();
}

__device__ __forceinline__ void aggInc(unsigned int* sh, unsigned int bucket) {
    unsigned int am = __activemask();
    unsigned int peers = __match_any_sync(am, bucket);
    int leader = __ffs(peers) - 1;
    if ((threadIdx.x & 31) == leader) atomicAdd(&sh[bucket], __popc(peers));
}

__device__ __forceinline__ void emit(unsigned int key, unsigned int idx, unsigned int T) {
    bool p = (key >= T);
    unsigned int am = __activemask();
    unsigned int bal = __ballot_sync(am, p);
    if (p) {
        int lane = threadIdx.x & 31;
        int leader = __ffs(bal) - 1;
        int base = 0;
        if (lane == leader) base = atomicAdd(&g_cand_cnt, __popc(bal));
        base = __shfl_sync(bal, base, leader);
        int slot = base + __popc(bal & ((1u << lane) - 1u));
        if (slot < CAP)
            g_cand[slot] = ((unsigned long long)key << 32) |
                           (unsigned long long)(0xFFFFFFFFu - idx);
    }
}

__device__ __forceinline__ void resolve256(const unsigned int* gh, unsigned int kth,
                                           unsigned int* shR,
                                           unsigned int* s_dig, unsigned int* s_kth) {
    int t = threadIdx.x;
    if (t < 256) shR[t] = gh[t];
    __syncthreads();
    for (int off = 1; off < 256; off <<= 1) {
        unsigned int v = 0, u = 0;
        if (t < 256) { v = shR[t]; u = (t + off < 256) ? shR[t + off] : 0u; }
        __syncthreads();
        if (t < 256) shR[t] = v + u;
        __syncthreads();
    }
    if (t < 256) {
        unsigned int e = (t < 255) ? shR[t + 1] : 0u;
        if (e < kth && shR[t] >= kth) { *s_dig = (unsigned int)t; *s_kth = kth - e; }
    }
    __syncthreads();
}

__device__ __forceinline__ float max20(const float4* r) {
    float a0 = fmaxf(fmaxf(r[0].x, r[0].y), fmaxf(r[0].z, r[0].w));
    float a1 = fmaxf(fmaxf(r[1].x, r[1].y), fmaxf(r[1].z, r[1].w));
    float a2 = fmaxf(fmaxf(r[2].x, r[2].y), fmaxf(r[2].z, r[2].w));
    float a3 = fmaxf(fmaxf(r[3].x, r[3].y), fmaxf(r[3].z, r[3].w));
    float a4 = fmaxf(fmaxf(r[4].x, r[4].y), fmaxf(r[4].z, r[4].w));
    return fmaxf(fmaxf(fmaxf(a0, a1), fmaxf(a2, a3)), a4);
}

// ---------------- the single fused kernel ----------------
extern "C" __global__ void __launch_bounds__(NTHR, 1)
nms_fused_kernel(const float* __restrict__ boxes,
                 const float* __restrict__ cls,
                 const float* __restrict__ det,
                 float* __restrict__ out) {
    extern __shared__ unsigned char dynsmem[];
    __shared__ unsigned int shH[256];
    __shared__ unsigned int shR[256];
    __shared__ unsigned int s_d1, s_k1, s_d2, s_k2, s_d3;
    __shared__ unsigned int keepw[32], wpref[32];
    __shared__ int  s_sel[MAXBOX];
    __shared__ int  s_nkeep;
    __shared__ unsigned int s_base;

    const int t    = threadIdx.x;
    const int blk  = blockIdx.x;
    const int gtid = blk * NTHR + t;
    const int lane = t & 31;
    const int warp = t >> 5;

    long long tp0 = 0, tp1 = 0, tp2 = 0, tp3 = 0, tp4 = 0, tp5 = 0, tp6 = 0, tp7 = 0;
    const bool timer = (blk == 0 && t == 0);

    if (t == 0) s_base = atomicAdd(&g_bar_gen, 0u);
    if (t < 256) shH[t] = 0u;
    __syncthreads();
    const unsigned int base = s_base;
    if (timer) tp0 = clock64();

    // ===== P1: 4-lanes-per-anchor max, register-only reduce =====
    {
        const float4* gp = (const float4*)cls;
        const int p = lane & 3;          // quarter within anchor
        const int a = lane >> 2;         // anchor slot (0..7)
        const int gwarp = blk * 32 + warp;
        for (int chunk = gwarp; chunk < NCH16; chunk += NWARPS) {
            const size_t b0 = (size_t)chunk * (16 * 20);   // f4 units
            float4 r0[5], r1[5];
            const size_t o0 = b0 + a * 20 + p;
            const size_t o1 = o0 + 160;                    // +8 anchors
#pragma unroll
            for (int j = 0; j < 5; j++) r0[j] = gp[o0 + 4 * j];
#pragma unroll
            for (int j = 0; j < 5; j++) r1[j] = gp[o1 + 4 * j];
            float m0 = max20(r0);
            float m1 = max20(r1);
            m0 = fmaxf(m0, __shfl_xor_sync(0xFFFFFFFFu, m0, 1));
            m0 = fmaxf(m0, __shfl_xor_sync(0xFFFFFFFFu, m0, 2));
            m1 = fmaxf(m1, __shfl_xor_sync(0xFFFFFFFFu, m1, 1));
            m1 = fmaxf(m1, __shfl_xor_sync(0xFFFFFFFFu, m1, 2));
            unsigned int k0 = __float_as_uint(m0);   // scores >= 0 -> monotonic
            unsigned int k1 = __float_as_uint(m1);
            if (p == 0) {
                int A0 = chunk * 16;
                g_scores[A0 + a]     = k0;
                g_scores[A0 + 8 + a] = k1;
                aggInc(shH, k0 >> 24);
                aggInc(shH, k1 >> 24);
            }
        }
    }
    __syncthreads();
    if (t < 256 && shH[t]) atomicAdd(&g_histA[t], shH[t]);
    gbar(base, 1, true);
    if (timer) tp1 = clock64();

    // ===== P2: resolve digit 1 + hist bits[23:16] =====
    resolve256(g_histA, TOPK, shR, &s_d1, &s_k1);
    if (t < 256) shH[t] = 0u;
    __syncthreads();
    {
        unsigned int d1 = s_d1;
        if (gtid < N_ANCH / 4) {
            uint4 k = ((const uint4*)g_scores)[gtid];
            if ((k.x >> 24) == d1) aggInc(shH, (k.x >> 16) & 255u);
            if ((k.y >> 24) == d1) aggInc(shH, (k.y >> 16) & 255u);
            if ((k.z >> 24) == d1) aggInc(shH, (k.z >> 16) & 255u);
            if ((k.w >> 24) == d1) aggInc(shH, (k.w >> 16) & 255u);
        }
    }
    __syncthreads();
    if (t < 256 && shH[t]) atomicAdd(&g_histB[t], shH[t]);
    gbar(base, 2, true);
    if (timer) tp2 = clock64();

    // ===== P3: resolve digit 2 + hist bits[15:8] =====
    resolve256(g_histB, s_k1, shR, &s_d2, &s_k2);
    if (t < 256) shH[t] = 0u;
    __syncthreads();
    {
        unsigned int pre16 = (s_d1 << 8) | s_d2;
        if (gtid < N_ANCH / 4) {
            uint4 k = ((const uint4*)g_scores)[gtid];
            if ((k.x >> 16) == pre16) aggInc(shH, (k.x >> 8) & 255u);
            if ((k.y >> 16) == pre16) aggInc(shH, (k.y >> 8) & 255u);
            if ((k.z >> 16) == pre16) aggInc(shH, (k.z >> 8) & 255u);
            if ((k.w >> 16) == pre16) aggInc(shH, (k.w >> 8) & 255u);
        }
    }
    __syncthreads();
    if (t < 256 && shH[t]) atomicAdd(&g_histC[t], shH[t]);
    gbar(base, 3, true);
    if (timer) tp3 = clock64();

    // ===== P4: resolve digit 3 -> threshold; warp-aggregated compact =====
    resolve256(g_histC, s_k2, shR, &s_d3, &s_k1 /*unused*/);
    {
        unsigned int T = (s_d1 << 24) | (s_d2 << 16) | (s_d3 << 8);
        if (gtid < N_ANCH / 4) {
            uint4 k = ((const uint4*)g_scores)[gtid];
            unsigned int bi = (unsigned int)(gtid * 4);
            emit(k.x, bi, T);
            emit(k.y, bi + 1, T);
            emit(k.z, bi + 2, T);
            emit(k.w, bi + 3, T);
        }
    }
    gbar(base, 4, true);
    if (timer) tp4 = clock64();

    // ===== P5: block0 sorts candidates + gathers boxes; block1 zeroes hists =====
    int dbg_cnt = 0;
    if (blk == 1) {
        if (t < 256) { g_histA[t] = 0u; g_histB[t] = 0u; g_histC[t] = 0u; }
    }
    if (blk == 0) {
        unsigned long long* scand = (unsigned long long*)dynsmem;
        int cnt = g_cand_cnt;
        dbg_cnt = cnt;
        __syncthreads();
        if (t == 0) g_cand_cnt = 0;
        if (cnt > CAP) cnt = CAP;
        int S = (cnt <= 2048) ? 2048 : CAP;
        for (int i = t; i < S; i += NTHR)
            scand[i] = (i < cnt) ? g_cand[i] : 0ull;
        __syncthreads();
        for (int k = 2; k <= S; k <<= 1) {
            for (int j = k >> 1; j > 0; j >>= 1) {
                for (int idx = t; idx < S; idx += NTHR) {
                    int l = idx ^ j;
                    if (l > idx) {
                        bool up = ((idx & k) == 0);
                        unsigned long long a = scand[idx], b = scand[l];
                        bool sw = up ? (a < b) : (a > b);
                        if (sw) { scand[idx] = b; scand[l] = a; }
                    }
                }
                __syncthreads();
            }
        }
        if (t < TOPK) {
            unsigned long long key = scand[t];
            int idx = (int)(0xFFFFFFFFu - (unsigned int)key);
            g_topk_idx[t] = idx;
            g_boxk[t] = ((const float4*)boxes)[idx];
        }
    }
    gbar(base, 5, true);
    if (timer) tp5 = clock64();

    // ===== P6: IoU bitmask, TRANSPOSED layout [colword][row] (bit-exact fp32) =====
    if (gtid < 32 * TOPK) {
        int wj = gtid / TOPK;            // column word
        int i  = gtid - wj * TOPK;       // row
        float4 bi = g_boxk[i];
        float ai = __fmul_rn(__fsub_rn(bi.z, bi.x), __fsub_rn(bi.w, bi.y));
        unsigned int bits = 0u;
        int j0 = wj * 32;
#pragma unroll 8
        for (int tt = 0; tt < 32; tt++) {
            int j = j0 + tt;
            if (j < TOPK) {
                float4 bj = g_boxk[j];
                float aj = __fmul_rn(__fsub_rn(bj.z, bj.x), __fsub_rn(bj.w, bj.y));
                float ih = fmaxf(__fsub_rn(fminf(bi.z, bj.z), fmaxf(bi.x, bj.x)), 0.0f);
                float iw = fmaxf(__fsub_rn(fminf(bi.w, bj.w), fmaxf(bi.y, bj.y)), 0.0f);
                float inter = __fmul_rn(ih, iw);
                float denom = __fadd_rn(__fsub_rn(__fadd_rn(ai, aj), inter), 1e-8f);
                float iou = __fdiv_rn(inter, denom);
                if (iou > NMS_THR) bits |= (1u << tt);
            }
        }
        g_maskmat[gtid] = bits;          // coalesced
    }
    gbar(base, 6, blk == 0);
    if (blk != 0) return;
    if (timer) tp6 = clock64();

    // ===== P7: block0 tiled greedy keep-scan (registers) + output gather =====
    {
        unsigned int* smask = (unsigned int*)dynsmem;   // [w*TOPK + r]
        for (int i = t; i < 32 * TOPK; i += NTHR) smask[i] = g_maskmat[i];
        __syncthreads();

        if (t < 32) {   // warp 0
            for (int tile = 0; tile < 32; tile++) {
                int r = tile * 32 + lane;
                int nrows = TOPK - tile * 32; if (nrows > 32) nrows = 32;
                bool base_i = false;
                unsigned int wt_i = 0u;
                if (r < TOPK) {
                    for (int w = 0; w < tile; w++)
                        base_i |= (keepw[w] & smask[w * TOPK + r]) != 0u;
                    wt_i = smask[tile * TOPK + r];
                }
                unsigned int bases = __ballot_sync(0xFFFFFFFFu, base_i);
                unsigned int keep_tile = 0u;
#pragma unroll
                for (int rr = 0; rr < 32; rr++) {
                    unsigned int word_r = __shfl_sync(0xFFFFFFFFu, wt_i, rr);
                    bool sup = ((bases >> rr) & 1u) ||
                               ((keep_tile & word_r & ((1u << rr) - 1u)) != 0u);
                    if (!sup && rr < nrows) keep_tile |= 1u << rr;
                }
                if (lane == 0) keepw[tile] = keep_tile;
                __syncwarp();
            }
            unsigned int kw = keepw[lane];
            unsigned int pc = __popc(kw);
            unsigned int inc = pc;
            for (int off = 1; off < 32; off <<= 1) {
                unsigned int v = __shfl_up_sync(0xFFFFFFFFu, inc, off);
                if (lane >= off) inc += v;
            }
            wpref[lane] = inc - pc;
            if (lane == 31) s_nkeep = (int)inc;
        }
        __syncthreads();

        if (t < TOPK) {
            int w = t >> 5, b = t & 31;
            unsigned int kw = keepw[w];
            if ((kw >> b) & 1u) {
                int rank = (int)wpref[w] + __popc(kw & ((1u << b) - 1u));
                if (rank < MAXBOX) s_sel[rank] = g_topk_idx[t];
            }
        }
        __syncthreads();

        int nk = s_nkeep;
        if (nk > MAXBOX) nk = MAXBOX;
        for (int e = t; e < MAXBOX * DET_DIM; e += NTHR) {
            int r = e / DET_DIM;
            int c = e - r * DET_DIM;
            out[e] = (r < nk) ? det[(size_t)s_sel[r] * DET_DIM + c] : 0.0f;
        }
    }
    __syncthreads();
    if (timer) {
        tp7 = clock64();
        printf("PHASES cyc: P1=%lld P2=%lld P3=%lld P4=%lld P5=%lld P6=%lld P7=%lld cnt=%d nk=%d\n",
               tp1 - tp0, tp2 - tp1, tp3 - tp2, tp4 - tp3, tp5 - tp4,
               tp6 - tp5, tp7 - tp6, dbg_cnt, s_nkeep);
    }
}

// ---------------- launch: ONE kernel ----------------
extern "C" void kernel_launch(void* const* d_in, const int* in_sizes, int n_in,
                              void* d_out, int out_size) {
    const float* boxes = (const float*)d_in[0];
    const float* cls   = (const float*)d_in[1];
    const float* det   = (const float*)d_in[2];
    float* out = (float*)d_out;

    cudaFuncSetAttribute((const void*)nms_fused_kernel,
                         cudaFuncAttributeMaxDynamicSharedMemorySize, DYN_BYTES);

    nms_fused_kernel<<<GRIDB, NTHR, DYN_BYTES>>>(boxes, cls, det, out);
}

// round 10
// speedup vs baseline: 1.2071x; 1.2071x over previous
#include <cuda_runtime.h>
#include <cstdint>

#define N_ANCH   300000
#define N_CLS    80
#define DET_DIM  85
#define TOPK     1000
#define MAXBOX   300
#define CAP      4096
#define NMS_THR  0.4f
#define H12      4096

#define GRIDB    148
#define NTHR     1024
#define NWARPS   (GRIDB * (NTHR / 32))     // 4736
#define NCH16    (N_ANCH / 16)             // 18750 (exact)
#define DYN_BYTES (TOPK * 32 * 4)          // 128000 B (hists 16K, rank 32K, scan 125K)

// ---------------- device scratch ----------------
__device__ unsigned int       g_scores[N_ANCH];
__device__ unsigned int       g_h12A[H12];          // bits[31:20]; re-zeroed each run (P5)
__device__ unsigned int       g_h12B[H12];          // bits[19:8] within winning d1
__device__ int                g_cand_cnt;           // reset in P5
__device__ unsigned long long g_cand[CAP];
__device__ int                g_topk_idx[TOPK];
__device__ float4             g_boxk[TOPK];
__device__ unsigned int       g_maskmat[32 * TOPK]; // TRANSPOSED: [colword][row]
__device__ unsigned int       g_bar_count;
__device__ unsigned int       g_bar_gen;

// ---------------- grid barrier ----------------
__device__ __forceinline__ void gbar(unsigned int base, unsigned int k, bool wait) {
    __syncthreads();
    if (threadIdx.x == 0) {
        __threadfence();
        unsigned int a = atomicAdd(&g_bar_count, 1u) + 1u;
        if (a == GRIDB) {
            g_bar_count = 0u;
            __threadfence();
            atomicExch(&g_bar_gen, base + k);
        } else if (wait) {
            const volatile unsigned int* vg = &g_bar_gen;
            while (*vg - base < k) __nanosleep(64);
            __threadfence();
        }
    }
    __syncthreads();
}

__device__ __forceinline__ void aggInc(unsigned int* sh, unsigned int bucket) {
    unsigned int am = __activemask();
    unsigned int peers = __match_any_sync(am, bucket);
    int leader = __ffs(peers) - 1;
    if ((threadIdx.x & 31) == leader) atomicAdd(&sh[bucket], __popc(peers));
}

__device__ __forceinline__ void emit(unsigned int key, unsigned int idx, unsigned int T) {
    bool p = (key >= T);
    unsigned int am = __activemask();
    unsigned int bal = __ballot_sync(am, p);
    if (p) {
        int lane = threadIdx.x & 31;
        int leader = __ffs(bal) - 1;
        int base = 0;
        if (lane == leader) base = atomicAdd(&g_cand_cnt, __popc(bal));
        base = __shfl_sync(bal, base, leader);
        int slot = base + __popc(bal & ((1u << lane) - 1u));
        if (slot < CAP)
            g_cand[slot] = ((unsigned long long)key << 32) |
                           (unsigned long long)(0xFFFFFFFFu - idx);
    }
}

// resolve a 4096-bin global hist: digit with kth-largest; updates kth remainder
__device__ __forceinline__ void resolve4096(const unsigned int* gh, unsigned int kth,
                                            unsigned int* suf,
                                            unsigned int* s_dig, unsigned int* s_kth) {
    int t = threadIdx.x;
    uint4 v = ((const uint4*)gh)[t];          // bins t*4..t*4+3
    suf[t] = v.x + v.y + v.z + v.w;
    __syncthreads();
    for (int off = 1; off < 1024; off <<= 1) {   // inclusive suffix scan
        unsigned int a = suf[t];
        unsigned int b = (t + off < 1024) ? suf[t + off] : 0u;
        __syncthreads();
        suf[t] = a + b;
        __syncthreads();
    }
    unsigned int excl = (t < 1023) ? suf[t + 1] : 0u;
    if (excl < kth && suf[t] >= kth) {        // unique winner thread
        unsigned int cum = excl;
        for (int b = 3; b >= 0; b--) {        // walk own 4 bins high->low
            unsigned int c = gh[t * 4 + b];
            if (cum + c >= kth) { *s_dig = (unsigned int)(t * 4 + b); *s_kth = kth - cum; break; }
            cum += c;
        }
    }
    __syncthreads();
}

__device__ __forceinline__ float max20(const float4* r) {
    float a0 = fmaxf(fmaxf(r[0].x, r[0].y), fmaxf(r[0].z, r[0].w));
    float a1 = fmaxf(fmaxf(r[1].x, r[1].y), fmaxf(r[1].z, r[1].w));
    float a2 = fmaxf(fmaxf(r[2].x, r[2].y), fmaxf(r[2].z, r[2].w));
    float a3 = fmaxf(fmaxf(r[3].x, r[3].y), fmaxf(r[3].z, r[3].w));
    float a4 = fmaxf(fmaxf(r[4].x, r[4].y), fmaxf(r[4].z, r[4].w));
    return fmaxf(fmaxf(fmaxf(a0, a1), fmaxf(a2, a3)), a4);
}

// ---------------- the single fused kernel ----------------
extern "C" __global__ void __launch_bounds__(NTHR, 1)
nms_fused_kernel(const float* __restrict__ boxes,
                 const float* __restrict__ cls,
                 const float* __restrict__ det,
                 float* __restrict__ out) {
    extern __shared__ unsigned char dynsmem[];
    __shared__ unsigned int suf[1024];
    __shared__ unsigned int s_d1, s_k1, s_d2, s_k2;
    __shared__ unsigned int keepw[32], wpref[32];
    __shared__ int  s_sel[MAXBOX];
    __shared__ int  s_nkeep;
    __shared__ unsigned int s_base;

    const int t    = threadIdx.x;
    const int blk  = blockIdx.x;
    const int gtid = blk * NTHR + t;
    const int lane = t & 31;
    const int warp = t >> 5;

    unsigned int* sh12 = (unsigned int*)dynsmem;   // 4096-bin smem hist (16KB)

    if (t == 0) s_base = atomicAdd(&g_bar_gen, 0u);
    for (int i = t; i < H12; i += NTHR) sh12[i] = 0u;
    __syncthreads();
    const unsigned int base = s_base;

    // ===== P1: 4-lanes-per-anchor max + smem hist on bits[31:20] =====
    {
        const float4* gp = (const float4*)cls;
        const int p = lane & 3;
        const int a = lane >> 2;
        const int gwarp = blk * 32 + warp;
        for (int chunk = gwarp; chunk < NCH16; chunk += NWARPS) {
            const size_t b0 = (size_t)chunk * (16 * 20);
            float4 r0[5], r1[5];
            const size_t o0 = b0 + a * 20 + p;
            const size_t o1 = o0 + 160;
#pragma unroll
            for (int j = 0; j < 5; j++) r0[j] = __ldcs(&gp[o0 + 4 * j]);
#pragma unroll
            for (int j = 0; j < 5; j++) r1[j] = __ldcs(&gp[o1 + 4 * j]);
            float m0 = max20(r0);
            float m1 = max20(r1);
            m0 = fmaxf(m0, __shfl_xor_sync(0xFFFFFFFFu, m0, 1));
            m0 = fmaxf(m0, __shfl_xor_sync(0xFFFFFFFFu, m0, 2));
            m1 = fmaxf(m1, __shfl_xor_sync(0xFFFFFFFFu, m1, 1));
            m1 = fmaxf(m1, __shfl_xor_sync(0xFFFFFFFFu, m1, 2));
            unsigned int k0 = __float_as_uint(m0);   // scores >= 0 -> monotonic
            unsigned int k1 = __float_as_uint(m1);
            if (p == 0) {
                int A0 = chunk * 16;
                g_scores[A0 + a]     = k0;
                g_scores[A0 + 8 + a] = k1;
                aggInc(sh12, k0 >> 20);
                aggInc(sh12, k1 >> 20);
            }
        }
    }
    __syncthreads();
    for (int i = t; i < H12; i += NTHR)
        if (sh12[i]) atomicAdd(&g_h12A[i], sh12[i]);
    gbar(base, 1, true);

    // ===== P2: resolve digit 1 (12b) + hist bits[19:8] restricted =====
    resolve4096(g_h12A, TOPK, suf, &s_d1, &s_k1);
    for (int i = t; i < H12; i += NTHR) sh12[i] = 0u;
    __syncthreads();
    {
        unsigned int d1 = s_d1;
        if (gtid < N_ANCH / 4) {
            uint4 k = ((const uint4*)g_scores)[gtid];
            if ((k.x >> 20) == d1) aggInc(sh12, (k.x >> 8) & 4095u);
            if ((k.y >> 20) == d1) aggInc(sh12, (k.y >> 8) & 4095u);
            if ((k.z >> 20) == d1) aggInc(sh12, (k.z >> 8) & 4095u);
            if ((k.w >> 20) == d1) aggInc(sh12, (k.w >> 8) & 4095u);
        }
    }
    __syncthreads();
    for (int i = t; i < H12; i += NTHR)
        if (sh12[i]) atomicAdd(&g_h12B[i], sh12[i]);
    gbar(base, 2, true);

    // ===== P3: resolve digit 2 -> 24-bit threshold; warp-aggregated compact =====
    resolve4096(g_h12B, s_k1, suf, &s_d2, &s_k2);
    {
        unsigned int T = (s_d1 << 20) | (s_d2 << 8);
        if (gtid < N_ANCH / 4) {
            uint4 k = ((const uint4*)g_scores)[gtid];
            unsigned int bi = (unsigned int)(gtid * 4);
            emit(k.x, bi, T);
            emit(k.y, bi + 1, T);
            emit(k.z, bi + 2, T);
            emit(k.w, bi + 3, T);
        }
    }
    gbar(base, 3, true);

    // ===== P4: grid-parallel rank-select (exact stable top-k) + box gather =====
    {
        int cnt = g_cand_cnt;
        if (cnt > CAP) cnt = CAP;
        if (blk * NTHR < cnt) {
            unsigned long long* sc = (unsigned long long*)dynsmem;
            for (int i = t; i < cnt; i += NTHR) sc[i] = g_cand[i];
            __syncthreads();
            int i = blk * NTHR + t;
            if (i < cnt) {
                unsigned long long key = sc[i];
                int rank = 0;
#pragma unroll 4
                for (int j = 0; j < cnt; j++) rank += (sc[j] > key);
                if (rank < TOPK) {
                    int idx = (int)(0xFFFFFFFFu - (unsigned int)key);
                    g_topk_idx[rank] = idx;
                    g_boxk[rank] = ((const float4*)boxes)[idx];
                }
            }
        }
    }
    gbar(base, 4, true);

    // ===== P5: IoU bitmask (transposed, bit-exact fp32) + scratch cleanup =====
    if (gtid < 32 * TOPK) {
        int wj = gtid / TOPK;
        int i  = gtid - wj * TOPK;
        float4 bi = g_boxk[i];
        float ai = __fmul_rn(__fsub_rn(bi.z, bi.x), __fsub_rn(bi.w, bi.y));
        unsigned int bits = 0u;
        int j0 = wj * 32;
#pragma unroll 8
        for (int tt = 0; tt < 32; tt++) {
            int j = j0 + tt;
            if (j < TOPK) {
                float4 bj = g_boxk[j];
                float aj = __fmul_rn(__fsub_rn(bj.z, bj.x), __fsub_rn(bj.w, bj.y));
                float ih = fmaxf(__fsub_rn(fminf(bi.z, bj.z), fmaxf(bi.x, bj.x)), 0.0f);
                float iw = fmaxf(__fsub_rn(fminf(bi.w, bj.w), fmaxf(bi.y, bj.y)), 0.0f);
                float inter = __fmul_rn(ih, iw);
                float denom = __fadd_rn(__fsub_rn(__fadd_rn(ai, aj), inter), 1e-8f);
                float iou = __fdiv_rn(inter, denom);
                if (iou > NMS_THR) bits |= (1u << tt);
            }
        }
        g_maskmat[gtid] = bits;
    }
    if (blk == 100) { for (int i = t; i < H12; i += NTHR) g_h12A[i] = 0u; }
    if (blk == 101) { for (int i = t; i < H12; i += NTHR) g_h12B[i] = 0u; }
    if (blk == 102 && t == 0) g_cand_cnt = 0;
    gbar(base, 5, blk == 0);
    if (blk != 0) return;

    // ===== P6: block0 tiled greedy keep-scan (registers) + output gather =====
    {
        unsigned int* smask = (unsigned int*)dynsmem;   // [w*TOPK + r]
        for (int i = t; i < 32 * TOPK; i += NTHR) smask[i] = g_maskmat[i];
        __syncthreads();

        if (t < 32) {   // warp 0
            for (int tile = 0; tile < 32; tile++) {
                int r = tile * 32 + lane;
                int nrows = TOPK - tile * 32; if (nrows > 32) nrows = 32;
                bool base_i = false;
                unsigned int wt_i = 0u;
                if (r < TOPK) {
                    for (int w = 0; w < tile; w++)
                        base_i |= (keepw[w] & smask[w * TOPK + r]) != 0u;
                    wt_i = smask[tile * TOPK + r];
                }
                unsigned int bases = __ballot_sync(0xFFFFFFFFu, base_i);
                unsigned int keep_tile = 0u;
#pragma unroll
                for (int rr = 0; rr < 32; rr++) {
                    unsigned int word_r = __shfl_sync(0xFFFFFFFFu, wt_i, rr);
                    bool sup = ((bases >> rr) & 1u) ||
                               ((keep_tile & word_r & ((1u << rr) - 1u)) != 0u);
                    if (!sup && rr < nrows) keep_tile |= 1u << rr;
                }
                if (lane == 0) keepw[tile] = keep_tile;
                __syncwarp();
            }
            unsigned int kw = keepw[lane];
            unsigned int pc = __popc(kw);
            unsigned int inc = pc;
            for (int off = 1; off < 32; off <<= 1) {
                unsigned int v = __shfl_up_sync(0xFFFFFFFFu, inc, off);
                if (lane >= off) inc += v;
            }
            wpref[lane] = inc - pc;
            if (lane == 31) s_nkeep = (int)inc;
        }
        __syncthreads();

        if (t < TOPK) {
            int w = t >> 5, b = t & 31;
            unsigned int kw = keepw[w];
            if ((kw >> b) & 1u) {
                int rank = (int)wpref[w] + __popc(kw & ((1u << b) - 1u));
                if (rank < MAXBOX) s_sel[rank] = g_topk_idx[t];
            }
        }
        __syncthreads();

        int nk = s_nkeep;
        if (nk > MAXBOX) nk = MAXBOX;
        for (int e = t; e < MAXBOX * DET_DIM; e += NTHR) {
            int r = e / DET_DIM;
            int c = e - r * DET_DIM;
            out[e] = (r < nk) ? det[(size_t)s_sel[r] * DET_DIM + c] : 0.0f;
        }
    }
}

// ---------------- launch: ONE kernel ----------------
extern "C" void kernel_launch(void* const* d_in, const int* in_sizes, int n_in,
                              void* d_out, int out_size) {
    const float* boxes = (const float*)d_in[0];
    const float* cls   = (const float*)d_in[1];
    const float* det   = (const float*)d_in[2];
    float* out = (float*)d_out;

    cudaFuncSetAttribute((const void*)nms_fused_kernel,
                         cudaFuncAttributeMaxDynamicSharedMemorySize, DYN_BYTES);

    nms_fused_kernel<<<GRIDB, NTHR, DYN_BYTES>>>(boxes, cls, det, out);
}